// round 17
// baseline (speedup 1.0000x reference)
#include <cuda_runtime.h>
#include <cuda_bf16.h>
#include <cuda_fp16.h>
#include <mma.h>

using namespace nvcuda;

#define BB    64
#define TXX   1024
#define AD    1024
#define UN    1024
#define VOC   32000
#define ED    512
#define NZ    4096
#define TCH   16

#define TP 72          // half/bf16 smem tile pitch: 64 + 8

// ---------------- scratch (__device__ globals; NEVER passed from host) ----------------
__device__ __align__(16) float g_pctx[TCH * BB * AD];
__device__ __align__(16) __nv_bfloat16 g_xz_hi[BB * AD];
__device__ __align__(16) __nv_bfloat16 g_xz_lo[BB * AD];
__device__ __align__(16) half g_xv_h16[BB * UN];
__device__ __align__(16) float g_z[BB * NZ];          // bias-seeded, atomically accumulated
__device__ __align__(16) float g_psum[BB * 512];      // per-(row, n-block) exp sums
__device__ float g_sinv[BB];

__device__ __forceinline__ float sigf(float x) { return 1.0f / (1.0f + __expf(-x)); }
__device__ __forceinline__ float tanhfast(float x) {
    float e = __expf(2.0f * x);
    return 1.0f - 2.0f / (e + 1.0f);
}

__device__ __forceinline__ void split_write(__nv_bfloat16* hi, __nv_bfloat16* lo,
                                            size_t idx, float v) {
    __nv_bfloat16 h = __float2bfloat16(v);
    hi[idx] = h;
    lo[idx] = __float2bfloat16(v - __bfloat162float(h));
}

// ---------------- K0: seed z with bias ----------------
__global__ void zinit(const float* __restrict__ bl) {
    int n = blockIdx.x * 256 + threadIdx.x;
    g_z[(size_t)blockIdx.y * NZ + n] = bl[n];
}

// ---------------- K1 fused: zgemm part-B (fp16, emb+h, 4 k-splits) + ctx partials ----------------
__global__ void __launch_bounds__(128, 4)
ctx_zb(const float* __restrict__ a, const int* __restrict__ X,
       const float* __restrict__ emb, const float* __restrict__ h,
       const float* __restrict__ Wx, const float* __restrict__ Wh) {
    __shared__ __align__(32) char smbuf[18432];
    int bid = blockIdx.x;
    int tid = threadIdx.x;

    if (bid >= 256) {
        int bb  = bid - 256;
        int b   = bb >> 5;
        int tch = bb & 15;
        int dh  = (bb >> 4) & 1;
        int d4  = dh * 128 + tid;
        int t0  = tch * 64;
        const float4* p = (const float4*)(a + ((size_t)b * TXX + t0) * AD) + d4;
        float4 s = make_float4(0.f, 0.f, 0.f, 0.f);
#pragma unroll 8
        for (int t = 0; t < 64; t++) {
            float4 v = p[(size_t)t * 256];
            s.x += v.x; s.y += v.y; s.z += v.z; s.w += v.w;
        }
        ((float4*)g_pctx)[((size_t)tch * BB + b) * 256 + d4] = s;
        return;
    }

    half* Ah = (half*)smbuf;
    half* Bh = Ah + 4608;
    int w  = tid >> 5;
    int n0 = (bid & 63) * 64;
    int ky = bid >> 6;                       // 0..3
    int k0 = ky * 384;
    const float* WxT = Wx + (size_t)AD * NZ;

    wmma::fragment<wmma::accumulator, 16, 16, 16, float> acc[4];
#pragma unroll
    for (int i = 0; i < 4; i++) wmma::fill_fragment(acc[i], 0.0f);

    float4 pa[8], pb[8];
    auto ldAB = [&](int kg0) {
#pragma unroll
        for (int i = 0; i < 8; i++) {
            int idx = tid + i * 128;
            int row = idx >> 4, f4c = idx & 15;
            const float* src = (kg0 < ED)
                ? (emb + (size_t)__ldg(X + row) * ED + kg0)
                : (h + (size_t)row * UN + (kg0 - ED));
            pa[i] = __ldg((const float4*)src + f4c);
        }
#pragma unroll
        for (int i = 0; i < 8; i++) {
            int idx = tid + i * 128;
            int k = idx >> 4, f4c = idx & 15;
            int kg = kg0 + k;
            const float* wrow = (kg < ED) ? (WxT + (size_t)kg * NZ)
                                          : (Wh + (size_t)(kg - ED) * NZ);
            pb[i] = __ldg((const float4*)(wrow + n0) + f4c);
        }
    };

    ldAB(k0);
#pragma unroll
    for (int ci = 0; ci < 6; ci++) {
        __syncthreads();
#pragma unroll
        for (int i = 0; i < 8; i++) {
            int idx = tid + i * 128;
            int row = idx >> 4, f4c = idx & 15;
            float4 v = pa[i];
            half2 h01 = __floats2half2_rn(v.x, v.y);
            half2 h23 = __floats2half2_rn(v.z, v.w);
            int ao = row * TP + f4c * 4;
            *(half2*)(Ah + ao)     = h01;
            *(half2*)(Ah + ao + 2) = h23;
        }
#pragma unroll
        for (int i = 0; i < 8; i++) {
            int idx = tid + i * 128;
            int k = idx >> 4, f4c = idx & 15;
            float4 v = pb[i];
            half2 h01 = __floats2half2_rn(v.x, v.y);
            half2 h23 = __floats2half2_rn(v.z, v.w);
            int bo = k * TP + f4c * 4;
            *(half2*)(Bh + bo)     = h01;
            *(half2*)(Bh + bo + 2) = h23;
        }
        __syncthreads();
        if (ci + 1 < 6) ldAB(k0 + (ci + 1) * 64);
#pragma unroll
        for (int kt = 0; kt < 4; kt++) {
            wmma::fragment<wmma::matrix_b, 16, 16, 16, half, wmma::row_major> bf;
            wmma::load_matrix_sync(bf, Bh + kt * 16 * TP + w * 16, TP);
            wmma::fragment<wmma::matrix_a, 16, 16, 16, half, wmma::row_major> af[4];
#pragma unroll
            for (int mt = 0; mt < 4; mt++)
                wmma::load_matrix_sync(af[mt], Ah + mt * 16 * TP + kt * 16, TP);
#pragma unroll
            for (int mt = 0; mt < 4; mt++) wmma::mma_sync(acc[mt], af[mt], bf, acc[mt]);
        }
    }
    __syncthreads();
    float* st = (float*)smbuf;
#pragma unroll
    for (int mt = 0; mt < 4; mt++)
        wmma::store_matrix_sync(st + mt * 16 * 64 + w * 16, acc[mt], 64, wmma::mem_row_major);
    __syncthreads();
#pragma unroll
    for (int i = 0; i < 32; i++) {
        int idx = tid + i * 128;
        int row = idx >> 6, col = idx & 63;
        atomicAdd(&g_z[(size_t)row * NZ + n0 + col], st[idx]);
    }
}

// ---------------- K2: finalize ctx + build bf16 ctx image ----------------
__global__ void ctx_finalize(float* __restrict__ o_ctx, float* __restrict__ o_alpha) {
    int b = blockIdx.y;
    int d = blockIdx.x * 256 + threadIdx.x;
    float s = 0.f;
#pragma unroll
    for (int j = 0; j < TCH; j++) s += g_pctx[((size_t)j * BB + b) * AD + d];
    o_ctx[b * AD + d]    = s;
    o_alpha[b * TXX + d] = 1.0f;
    split_write(g_xz_hi, g_xz_lo, (size_t)b * AD + d, s);
}

// ---------------- zgemm part-A: bf16 hi/lo 3-term on ctx rows ----------------
__global__ void __launch_bounds__(128, 4)
zgemmA(const float* __restrict__ Wx) {
    __shared__ __align__(32) char smbuf[36864];
    __nv_bfloat16* Ah = (__nv_bfloat16*)smbuf;
    __nv_bfloat16* Al = Ah + 4608;
    __nv_bfloat16* Bh = Ah + 9216;
    __nv_bfloat16* Bl = Ah + 13824;
    int tid = threadIdx.x, w = tid >> 5;
    int n0 = blockIdx.x * 64;
    int ky = blockIdx.y;
    int k0 = ky * 128;

    wmma::fragment<wmma::accumulator, 16, 16, 16, float> acc[4];
#pragma unroll
    for (int i = 0; i < 4; i++) wmma::fill_fragment(acc[i], 0.0f);

    float4 pf[8];
    auto ldB = [&](int kg0) {
#pragma unroll
        for (int i = 0; i < 8; i++) {
            int idx = tid + i * 128;
            int k = idx >> 4, f4c = idx & 15;
            pf[i] = __ldg((const float4*)(Wx + (size_t)(kg0 + k) * NZ + n0) + f4c);
        }
    };
    ldB(k0);
#pragma unroll
    for (int ci = 0; ci < 2; ci++) {
        int kg0 = k0 + ci * 64;
        __syncthreads();
#pragma unroll
        for (int i = 0; i < 4; i++) {
            int idx = tid + i * 128;
            int row = idx >> 3, j = idx & 7;
            size_t so = ((size_t)row * AD + kg0) / 8 + j;
            ((uint4*)Ah)[row * 9 + j] = ((const uint4*)g_xz_hi)[so];
            ((uint4*)Al)[row * 9 + j] = ((const uint4*)g_xz_lo)[so];
        }
#pragma unroll
        for (int i = 0; i < 8; i++) {
            int idx = tid + i * 128;
            int k = idx >> 4, f4c = idx & 15;
            float4 v = pf[i];
            __nv_bfloat16 h0 = __float2bfloat16(v.x), h1 = __float2bfloat16(v.y);
            __nv_bfloat16 h2 = __float2bfloat16(v.z), h3 = __float2bfloat16(v.w);
            __nv_bfloat16 l0 = __float2bfloat16(v.x - __bfloat162float(h0));
            __nv_bfloat16 l1 = __float2bfloat16(v.y - __bfloat162float(h1));
            __nv_bfloat16 l2 = __float2bfloat16(v.z - __bfloat162float(h2));
            __nv_bfloat16 l3 = __float2bfloat16(v.w - __bfloat162float(h3));
            int bo = k * TP + f4c * 4;
            *(__nv_bfloat162*)(Bh + bo)     = __halves2bfloat162(h0, h1);
            *(__nv_bfloat162*)(Bh + bo + 2) = __halves2bfloat162(h2, h3);
            *(__nv_bfloat162*)(Bl + bo)     = __halves2bfloat162(l0, l1);
            *(__nv_bfloat162*)(Bl + bo + 2) = __halves2bfloat162(l2, l3);
        }
        __syncthreads();
        if (ci == 0) ldB(kg0 + 64);
#pragma unroll
        for (int kt = 0; kt < 4; kt++) {
            wmma::fragment<wmma::matrix_b, 16, 16, 16, __nv_bfloat16, wmma::row_major> bh, bl;
            wmma::load_matrix_sync(bh, Bh + kt * 16 * TP + w * 16, TP);
            wmma::load_matrix_sync(bl, Bl + kt * 16 * TP + w * 16, TP);
            wmma::fragment<wmma::matrix_a, 16, 16, 16, __nv_bfloat16, wmma::row_major> af[4];
#pragma unroll
            for (int mt = 0; mt < 4; mt++)
                wmma::load_matrix_sync(af[mt], Ah + mt * 16 * TP + kt * 16, TP);
#pragma unroll
            for (int mt = 0; mt < 4; mt++) wmma::mma_sync(acc[mt], af[mt], bh, acc[mt]);
#pragma unroll
            for (int mt = 0; mt < 4; mt++) wmma::mma_sync(acc[mt], af[mt], bl, acc[mt]);
#pragma unroll
            for (int mt = 0; mt < 4; mt++)
                wmma::load_matrix_sync(af[mt], Al + mt * 16 * TP + kt * 16, TP);
#pragma unroll
            for (int mt = 0; mt < 4; mt++) wmma::mma_sync(acc[mt], af[mt], bh, acc[mt]);
        }
    }
    __syncthreads();
    float* st = (float*)smbuf;
#pragma unroll
    for (int mt = 0; mt < 4; mt++)
        wmma::store_matrix_sync(st + mt * 16 * 64 + w * 16, acc[mt], 64, wmma::mem_row_major);
    __syncthreads();
#pragma unroll
    for (int i = 0; i < 32; i++) {
        int idx = tid + i * 128;
        int row = idx >> 6, col = idx & 63;
        atomicAdd(&g_z[(size_t)row * NZ + n0 + col], st[idx]);
    }
}

// ---------------- vgemm16 + fused exp epilogue -> o_y + per-row partial sums ----------------
__global__ void __launch_bounds__(128, 4)
vgemm16(const float* __restrict__ Wv, const float* __restrict__ bv,
        float* __restrict__ o_y) {
    __shared__ __align__(32) char smbuf[18432];
    half* Ah = (half*)smbuf;
    half* Bh = Ah + 4608;

    int tid = threadIdx.x, w = tid >> 5;
    int n0 = blockIdx.x * 64;

    wmma::fragment<wmma::accumulator, 16, 16, 16, float> acc[4];
#pragma unroll
    for (int i = 0; i < 4; i++) wmma::fill_fragment(acc[i], 0.0f);

    uint4  pa[4];
    float4 pb[8];
    auto ldAB = [&](int kg0) {
#pragma unroll
        for (int i = 0; i < 4; i++) {
            int idx = tid + i * 128;
            int row = idx >> 3, j = idx & 7;
            pa[i] = ((const uint4*)g_xv_h16)[(size_t)row * (UN / 8) + kg0 / 8 + j];
        }
#pragma unroll
        for (int i = 0; i < 8; i++) {
            int idx = tid + i * 128;
            int k = idx >> 4, f4c = idx & 15;
            pb[i] = __ldg((const float4*)(Wv + (size_t)(kg0 + k) * VOC + n0) + f4c);
        }
    };

    ldAB(0);
    for (int ci = 0; ci < UN / 64; ci++) {
        __syncthreads();
#pragma unroll
        for (int i = 0; i < 4; i++) {
            int idx = tid + i * 128;
            int row = idx >> 3, j = idx & 7;
            ((uint4*)Ah)[row * 9 + j] = pa[i];
        }
#pragma unroll
        for (int i = 0; i < 8; i++) {
            int idx = tid + i * 128;
            int k = idx >> 4, f4c = idx & 15;
            float4 v = pb[i];
            half2 h01 = __floats2half2_rn(v.x, v.y);
            half2 h23 = __floats2half2_rn(v.z, v.w);
            int bo = k * TP + f4c * 4;
            *(half2*)(Bh + bo)     = h01;
            *(half2*)(Bh + bo + 2) = h23;
        }
        __syncthreads();
        if (ci + 1 < UN / 64) ldAB((ci + 1) * 64);
#pragma unroll
        for (int kt = 0; kt < 4; kt++) {
            wmma::fragment<wmma::matrix_b, 16, 16, 16, half, wmma::row_major> bf;
            wmma::load_matrix_sync(bf, Bh + kt * 16 * TP + w * 16, TP);
            wmma::fragment<wmma::matrix_a, 16, 16, 16, half, wmma::row_major> af[4];
#pragma unroll
            for (int mt = 0; mt < 4; mt++)
                wmma::load_matrix_sync(af[mt], Ah + mt * 16 * TP + kt * 16, TP);
#pragma unroll
            for (int mt = 0; mt < 4; mt++) wmma::mma_sync(acc[mt], af[mt], bf, acc[mt]);
        }
    }
    // ---- epilogue: logits tile -> smem, add bv, exp ONCE, write o_y, row partial sums ----
    __syncthreads();
    float* st = (float*)smbuf;               // 64x64 fp32 = 16384 B
#pragma unroll
    for (int mt = 0; mt < 4; mt++)
        wmma::store_matrix_sync(st + mt * 16 * 64 + w * 16, acc[mt], 64, wmma::mem_row_major);
    __syncthreads();
    int row = tid >> 1, hf = tid & 1;
    const float4* sr  = (const float4*)(st + row * 64) + hf * 8;
    const float4* bv4 = (const float4*)(bv + n0) + hf * 8;
    float4* oy = (float4*)(o_y + (size_t)row * VOC + n0) + hf * 8;
    float s = 0.f;
#pragma unroll
    for (int j = 0; j < 8; j++) {
        float4 v = sr[j], bb = bv4[j];
        float4 e = make_float4(__expf(v.x + bb.x), __expf(v.y + bb.y),
                               __expf(v.z + bb.z), __expf(v.w + bb.w));
        oy[j] = e;
        s += e.x + e.y + e.z + e.w;
    }
    s += __shfl_xor_sync(0xffffffffu, s, 1);
    if (hf == 0) g_psum[row * 512 + blockIdx.x] = s;
}

// ---------------- K4: LSTM gates (z pre-reduced, bias included) ----------------
__global__ void __launch_bounds__(128)
gates(const float* __restrict__ c,
      float* __restrict__ o_h, float* __restrict__ o_c) {
    int b = blockIdx.y;
    int u = blockIdx.x * 128 + threadIdx.x;     // grid.x = 8
    const float* z = g_z + (size_t)b * NZ;
    float zi = z[u], zf = z[u + UN], zg = z[u + 2 * UN], zo = z[u + 3 * UN];
    float cn = sigf(zf) * c[b * UN + u] + sigf(zi) * tanhfast(zg);
    float hn = sigf(zo) * tanhfast(cn);
    o_c[b * UN + u] = cn;
    o_h[b * UN + u] = hn;
    g_xv_h16[(size_t)b * UN + u] = __float2half_rn(hn);
}

// ---------------- sreduce: S[b] = sum of 500 partial sums; store 1/S ----------------
__global__ void sreduce() {
    int b = blockIdx.x, tid = threadIdx.x;      // 128 threads
    __shared__ float red[128];
    float s = 0.f;
    for (int i = tid; i < 500; i += 128) s += g_psum[b * 512 + i];
    red[tid] = s; __syncthreads();
    for (int k = 64; k > 0; k >>= 1) {
        if (tid < k) red[tid] += red[tid + k];
        __syncthreads();
    }
    if (tid == 0) g_sinv[b] = 1.0f / red[0];
}

// ---------------- sscale: o_y *= 1/S (pure memory pass) ----------------
__global__ void sscale(float* __restrict__ o_y) {
    int b = blockIdx.y, sl = blockIdx.x, tid = threadIdx.x;
    float inv = g_sinv[b];
    float4* oy4 = (float4*)(o_y + (size_t)b * VOC) + sl * 1000;
    for (int n = tid; n < 1000; n += 256) {
        float4 e = oy4[n];
        e.x *= inv; e.y *= inv; e.z *= inv; e.w *= inv;
        oy4[n] = e;
    }
}

// ---------------- launch ----------------
extern "C" void kernel_launch(void* const* d_in, const int* in_sizes, int n_in,
                              void* d_out, int out_size) {
    (void)in_sizes; (void)n_in; (void)out_size;
    const int*   X   = (const int*)d_in[0];
    const float* a   = (const float*)d_in[1];
    const float* h   = (const float*)d_in[2];
    const float* c   = (const float*)d_in[3];
    const float* emb = (const float*)d_in[4];
    // d_in[5..10] dead (softmax over size-1 axis == 1)
    const float* Wx  = (const float*)d_in[11];
    const float* Wh  = (const float*)d_in[12];
    const float* bl  = (const float*)d_in[13];
    const float* Wv  = (const float*)d_in[14];
    const float* bv  = (const float*)d_in[15];

    float* out     = (float*)d_out;
    float* o_y     = out;
    float* o_ctx   = o_y + (size_t)BB * VOC;
    float* o_alpha = o_ctx + BB * AD;
    float* o_h     = o_alpha + BB * TXX;
    float* o_c     = o_h + BB * UN;

    zinit<<<dim3(16, 64), 256>>>(bl);
    ctx_zb<<<2304, 128>>>(a, X, emb, h, Wx, Wh);
    ctx_finalize<<<dim3(4, 64), 256>>>(o_ctx, o_alpha);
    zgemmA<<<dim3(NZ / 64, 8), 128>>>(Wx);
    gates<<<dim3(8, 64), 128>>>(c, o_h, o_c);
    vgemm16<<<dim3(VOC / 64, 1), 128>>>(Wv, bv, o_y);
    sreduce<<<64, 128>>>();
    sscale<<<dim3(8, 64), 256>>>(o_y);
}